// round 12
// baseline (speedup 1.0000x reference)
#include <cuda_runtime.h>
#include <cuda_fp16.h>
#include <cstdint>

// ---------------------------------------------------------------------------
// Problem constants
// ---------------------------------------------------------------------------
#define B_ 4
#define N_ 4096
#define M_ 4096
#define C_ 512
#define R_ (B_ * N_)                     // 16384 rows
static const long NM_ = (long)N_ * M_;   // 16,777,216 per batch

#define BK 64
#define ROWB 144                  // 64 fp16 = 128B + 16B pad (conflict-free)
#define A_TILE (128 * ROWB)       // 18432 B
#define B_TILE (64 * ROWB)        //  9216 B
#define STAGE_B (A_TILE + B_TILE) // 27648 B  (128x64 kernels)

// 128x128 scores kernel tiles
#define S_ATILE (128 * ROWB)      // 18432
#define S_STAGE (2 * S_ATILE)     // 36864
#define S_SMEM  (2 * S_STAGE)     // 73728 (2-stage)

__device__ __forceinline__ uint32_t smem_u32(const void* p) {
    uint32_t a;
    asm("{ .reg .u64 t; cvta.to.shared.u64 t, %1; cvt.u32.u64 %0, t; }" : "=r"(a) : "l"(p));
    return a;
}

#define LDSM4(r, addr) \
    asm volatile("ldmatrix.sync.aligned.m8n8.x4.shared.b16 {%0,%1,%2,%3}, [%4];" \
                 : "=r"((r)[0]), "=r"((r)[1]), "=r"((r)[2]), "=r"((r)[3]) : "r"(addr))

#define MMA(dd, aa, b0, b1) \
    asm volatile("mma.sync.aligned.m16n8k16.row.col.f32.f16.f16.f32 " \
                 "{%0,%1,%2,%3}, {%4,%5,%6,%7}, {%8,%9}, {%0,%1,%2,%3};" \
                 : "+f"((dd)[0]), "+f"((dd)[1]), "+f"((dd)[2]), "+f"((dd)[3]) \
                 : "r"((aa)[0]), "r"((aa)[1]), "r"((aa)[2]), "r"((aa)[3]), \
                   "r"(b0), "r"(b1))

#define CP16(saddr, gptr) \
    asm volatile("cp.async.cg.shared.global [%0], [%1], 16;" :: "r"(saddr), "l"(gptr))

#define CP_COMMIT() asm volatile("cp.async.commit_group;" ::: "memory")
#define CP_WAIT(n)  asm volatile("cp.async.wait_group %0;" :: "n"(n) : "memory")

// ---------------------------------------------------------------------------
// Scratch
// ---------------------------------------------------------------------------
__device__ __half g_rgb[R_ * C_];
__device__ __half g_dep[R_ * C_];
__device__ __half g_wt[3 * C_ * C_];             // W^T for q,k,v: [co][c]
__device__ __half g_q[R_ * C_];
__device__ __half g_k[R_ * C_];
__device__ __half g_vt[(long)B_ * C_ * M_];      // V^T per batch: [b][c][m]
__device__ __half g_p[(long)B_ * N_ * M_];       // unnormalized exp (128 MB)
__device__ float  g_partial[(long)R_ * 32];      // per (row, 128-coltile) exp sums
__device__ float  g_rinv[R_];                    // 1 / rowsum

// ---------------------------------------------------------------------------
// Conversion kernel
// ---------------------------------------------------------------------------
#define NIN (R_ * C_)
#define NV4 (NIN / 4)
#define WCNT (C_ * C_)

__global__ void __launch_bounds__(256) convert_all(
    const float* __restrict__ rgb, const float* __restrict__ dep,
    const float* __restrict__ Wq, const float* __restrict__ Wk,
    const float* __restrict__ Wv,
    __half* __restrict__ orgb, __half* __restrict__ odep,
    __half* __restrict__ owt)
{
    int i = blockIdx.x * blockDim.x + threadIdx.x;
    if (i < 2 * NV4) {
        const float4* src = (i < NV4) ? (const float4*)rgb : (const float4*)dep;
        __half* dst = (i < NV4) ? orgb : odep;
        int j = (i < NV4) ? i : i - NV4;
        float4 v = src[j];
        __half2 h0, h1;
        h0.x = __float2half_rn(v.x); h0.y = __float2half_rn(v.y);
        h1.x = __float2half_rn(v.z); h1.y = __float2half_rn(v.w);
        *(__half2*)(dst + j * 4)     = h0;
        *(__half2*)(dst + j * 4 + 2) = h1;
    } else {
        int j = i - 2 * NV4;
        if (j < 3 * WCNT) {
            const float* W = (j < WCNT) ? Wq : (j < 2 * WCNT) ? Wk : Wv;
            int t = (j < WCNT) ? j : (j < 2 * WCNT) ? j - WCNT : j - 2 * WCNT;
            int co = t >> 9, c = t & 511;
            owt[j] = __float2half_rn(W[c * C_ + co]);
        }
    }
}

// ---------------------------------------------------------------------------
// Rowsum reduce: 32 partials per row -> 1/sum
// ---------------------------------------------------------------------------
__global__ void rowsum_kernel(const float* __restrict__ partial,
                              float* __restrict__ rinv) {
    int i = blockIdx.x * blockDim.x + threadIdx.x;   // 0..R_-1
    const float4* p = (const float4*)(partial + (long)i * 32);
    float s = 0.f;
    #pragma unroll
    for (int j = 0; j < 8; j++) {
        float4 v = p[j];
        s += (v.x + v.y) + (v.z + v.w);
    }
    rinv[i] = 1.0f / s;
}

// ---------------------------------------------------------------------------
// SCORES kernel: CTA 128x128, 4 warps, warp tile 64x64 (2x2 warp grid),
// 2-stage cp.async, 2 CTAs/SM.  32 independent HMMA chains per warp per step.
// P = exp2(S * scale2) fp16 + deterministic partial row sums.
// ---------------------------------------------------------------------------
__global__ void __launch_bounds__(128, 2) scores_k(
    const __half* __restrict__ Q, const __half* __restrict__ K,
    float scale2, __half* __restrict__ P, float* __restrict__ partial)
{
    extern __shared__ char smem[];
    const uint32_t sb = smem_u32(smem);
    const int tid = threadIdx.x, lane = tid & 31, wid = tid >> 5;
    const int wm = wid >> 1, wn = wid & 1;          // warp grid 2 x 2
    const int bx = blockIdx.x, by = blockIdx.y, bz = blockIdx.z;

    constexpr int kIters = C_ / BK;                 // 8

    // ---- cp.async: each thread owns one A row and one B row (8 CP16 each)
    const __half* pA = Q + (long)bz * ((long)N_ * C_) + (long)(bx * 128 + tid) * C_;
    const __half* pB = K + (long)bz * ((long)M_ * C_) + (long)(by * 128 + tid) * C_;
    const uint32_t sstA = sb + (uint32_t)tid * ROWB;
    const uint32_t sstB = sb + S_ATILE + (uint32_t)tid * ROWB;

    auto issue = [&](int kt, uint32_t so) {
        const int off = kt * BK;
        #pragma unroll
        for (int c = 0; c < 8; c++) {
            CP16(sstA + so + c * 16, pA + off + c * 8);
            CP16(sstB + so + c * 16, pB + off + c * 8);
        }
    };

    // ---- LDSM bases
    const uint32_t ldsmA = sb + (wm * 64 + (lane & 15)) * ROWB + (lane >> 4) * 16;
    const uint32_t ldsmB = sb + S_ATILE + (wn * 64 + (lane & 15)) * ROWB + (lane >> 4) * 16;

    float d[4][8][4];
    #pragma unroll
    for (int i = 0; i < 4; i++)
        #pragma unroll
        for (int j = 0; j < 8; j++)
            #pragma unroll
            for (int e = 0; e < 4; e++) d[i][j][e] = 0.f;

    issue(0, 0);
    CP_COMMIT();

    #pragma unroll 1
    for (int kb = 0; kb < kIters; kb += 2) {
        #pragma unroll
        for (int i = 0; i < 2; i++) {
            const int kt = kb + i;
            CP_WAIT(0);
            __syncthreads();
            if (kt + 1 < kIters)
                issue(kt + 1, ((i + 1) & 1) * S_STAGE);
            CP_COMMIT();

            const uint32_t so = i * S_STAGE;
            #pragma unroll
            for (int s = 0; s < 4; s++) {            // four k16 steps
                uint32_t ah[4][4], bh[8][2];
                const uint32_t coff = so + s * 32;
                #pragma unroll
                for (int mt = 0; mt < 4; mt++)
                    LDSM4(ah[mt], ldsmA + coff + mt * (16 * ROWB));
                #pragma unroll
                for (int np = 0; np < 4; np++) {
                    uint32_t r[4];
                    LDSM4(r, ldsmB + coff + np * (16 * ROWB));
                    bh[2 * np][0] = r[0]; bh[2 * np][1] = r[2];
                    bh[2 * np + 1][0] = r[1]; bh[2 * np + 1][1] = r[3];
                }
                #pragma unroll
                for (int mt = 0; mt < 4; mt++)
                    #pragma unroll
                    for (int nt = 0; nt < 8; nt++)
                        MMA(d[mt][nt], ah[mt], bh[nt][0], bh[nt][1]);
            }
        }
    }

    // ---- epilogue: exp2, store P, partial row sums
    const int mbase = bx * 128 + wm * 64;
    const int nbase = by * 128 + wn * 64;
    const int lr = lane >> 2;            // 0..7
    const int lc = (lane & 3) * 2;       // 0,2,4,6

    float esum[4][2];
    #pragma unroll
    for (int i = 0; i < 4; i++) { esum[i][0] = 0.f; esum[i][1] = 0.f; }

    #pragma unroll
    for (int mt = 0; mt < 4; mt++) {
        #pragma unroll
        for (int nt = 0; nt < 8; nt++) {
            #pragma unroll
            for (int h = 0; h < 2; h++) {
                const int m = mbase + mt * 16 + lr + h * 8;
                const int n = nbase + nt * 8 + lc;
                float e0 = exp2f(d[mt][nt][h * 2 + 0] * scale2);
                float e1 = exp2f(d[mt][nt][h * 2 + 1] * scale2);
                esum[mt][h] += e0 + e1;
                __half2 hv;
                hv.x = __float2half_rn(e0); hv.y = __float2half_rn(e1);
                *(__half2*)(P + (long)bz * NM_ + (long)m * M_ + n) = hv;
            }
        }
    }

    // deterministic partial sums: quad shfl -> smem -> global
    CP_WAIT(0);
    __syncthreads();
    float* sred = (float*)smem;          // [2 warp-cols][128 rows]
    #pragma unroll
    for (int mt = 0; mt < 4; mt++) {
        #pragma unroll
        for (int h = 0; h < 2; h++) {
            float v = esum[mt][h];
            v += __shfl_xor_sync(0xFFFFFFFFu, v, 1);
            v += __shfl_xor_sync(0xFFFFFFFFu, v, 2);
            if ((lane & 3) == 0)
                sred[wn * 128 + wm * 64 + mt * 16 + h * 8 + lr] = v;
        }
    }
    __syncthreads();
    if (tid < 128) {
        float s = sred[tid] + sred[128 + tid];
        partial[((long)(bz * N_ + bx * 128 + tid)) * 32 + by] = s;
    }
}

// ---------------------------------------------------------------------------
// Templated fp16 GEMM (proj + PV): CTA 128x64, 8 warps, warp 32x32.
// MODE 0: out fp16 row-major [row, C_], +bias[col]            (Q/K proj)
// MODE 1: out fp16 transposed [b][col][m], +bias[col]         (V^T proj)
// MODE 3: out fp32 * rinv[row], ld=C_                         (final)
// ---------------------------------------------------------------------------
template <int MODE, int KTOT, int NSTAGE, int MAXCTA>
__global__ void __launch_bounds__(256, MAXCTA) gemm_t(
    const __half* __restrict__ A, const __half* __restrict__ Bp,
    long aBatch, long bBatch,
    const float* __restrict__ bias,
    float* __restrict__ outF, __half* __restrict__ outH,
    const float* __restrict__ rinv)
{
    extern __shared__ char smem[];
    const uint32_t sb = smem_u32(smem);
    const int tid = threadIdx.x, lane = tid & 31, wid = tid >> 5;
    const int wm = wid >> 1, wn = wid & 1;          // warp grid 4(M) x 2(N)
    const int bx = blockIdx.x, by = blockIdx.y, bz = blockIdx.z;

    constexpr int kIters = KTOT / BK;

    const int arow = tid >> 1, ahalf = tid & 1;
    const __half* pA = A + bz * aBatch + (long)(bx * 128 + arow) * KTOT + ahalf * 32;
    const uint32_t sstA = sb + (uint32_t)arow * ROWB + ahalf * 64;
    const int brow = tid >> 2, bq4 = tid & 3;
    const __half* pB = Bp + bz * bBatch + (long)(by * 64 + brow) * KTOT + bq4 * 16;
    const uint32_t sstB = sb + A_TILE + (uint32_t)brow * ROWB + bq4 * 32;

    const uint32_t ldsmA = sb + (wm * 32 + (lane & 15)) * ROWB + (lane >> 4) * 16;
    const uint32_t ldsmB = sb + A_TILE + (wn * 32 + (lane & 15)) * ROWB + (lane >> 4) * 16;

    float d[2][4][4];
    #pragma unroll
    for (int i = 0; i < 2; i++)
        #pragma unroll
        for (int j = 0; j < 4; j++)
            #pragma unroll
            for (int e = 0; e < 4; e++) d[i][j][e] = 0.f;

    auto issue = [&](int kt, uint32_t so) {
        const int off = kt * BK;
        #pragma unroll
        for (int c = 0; c < 4; c++)
            CP16(sstA + so + c * 16, pA + off + c * 8);
        CP16(sstB + so,      pB + off);
        CP16(sstB + so + 16, pB + off + 8);
    };

    auto compute = [&](uint32_t so) {
        #pragma unroll
        for (int s = 0; s < 4; s++) {
            uint32_t ah[2][4], bh[4][2];
            const uint32_t coff = so + s * 32;
            #pragma unroll
            for (int mt = 0; mt < 2; mt++)
                LDSM4(ah[mt], ldsmA + coff + mt * (16 * ROWB));
            #pragma unroll
            for (int np = 0; np < 2; np++) {
                uint32_t r[4];
                LDSM4(r, ldsmB + coff + np * (16 * ROWB));
                bh[2 * np][0] = r[0]; bh[2 * np][1] = r[2];
                bh[2 * np + 1][0] = r[1]; bh[2 * np + 1][1] = r[3];
            }
            #pragma unroll
            for (int mt = 0; mt < 2; mt++)
                #pragma unroll
                for (int nt = 0; nt < 4; nt++)
                    MMA(d[mt][nt], ah[mt], bh[nt][0], bh[nt][1]);
        }
    };

    #pragma unroll
    for (int i = 0; i < NSTAGE - 1; i++) {
        issue(i, i * STAGE_B);
        CP_COMMIT();
    }

    #pragma unroll 1
    for (int kb = 0; kb < kIters; kb += NSTAGE) {
        #pragma unroll
        for (int i = 0; i < NSTAGE; i++) {
            const int kt = kb + i;
            CP_WAIT(NSTAGE - 2);
            __syncthreads();
            const int kpre = kt + NSTAGE - 1;
            if (kpre < kIters)
                issue(kpre, ((i + NSTAGE - 1) % NSTAGE) * STAGE_B);
            CP_COMMIT();
            compute(i * STAGE_B);
        }
    }

    const int mbase = bx * 128 + wm * 32;
    const int nbase = by * 64 + wn * 32;
    const int lr = lane >> 2;
    const int lc = (lane & 3) * 2;

    #pragma unroll
    for (int mt = 0; mt < 2; mt++) {
        #pragma unroll
        for (int nt = 0; nt < 4; nt++) {
            #pragma unroll
            for (int h = 0; h < 2; h++) {
                const int m = mbase + mt * 16 + lr + h * 8;
                const int n = nbase + nt * 8 + lc;
                float v0 = d[mt][nt][h * 2 + 0];
                float v1 = d[mt][nt][h * 2 + 1];
                if constexpr (MODE == 0) {
                    v0 += bias[n]; v1 += bias[n + 1];
                    __half2 hv;
                    hv.x = __float2half_rn(v0); hv.y = __float2half_rn(v1);
                    *(__half2*)(outH + (long)m * C_ + n) = hv;
                } else if constexpr (MODE == 1) {
                    v0 += bias[n]; v1 += bias[n + 1];
                    const int b = m >> 12, mm = m & 4095;
                    const long idx = (long)b * ((long)C_ * M_) + (long)n * M_ + mm;
                    outH[idx]      = __float2half_rn(v0);
                    outH[idx + M_] = __float2half_rn(v1);
                } else {
                    const float r = rinv[bz * N_ + m];
                    const long idx = (long)bz * ((long)N_ * C_) + (long)m * C_ + n;
                    float2 v; v.x = v0 * r; v.y = v1 * r;
                    *(float2*)(outF + idx) = v;
                }
            }
        }
    }
}

// ---------------------------------------------------------------------------
// Host launch.  ncu captures launch #4 -> SCORES there:
//   1 convert, 2 projQ, 3 projK, 4 SCORES (ncu), 5 projV, 6 rowsum, 7 PV
// ---------------------------------------------------------------------------
extern "C" void kernel_launch(void* const* d_in, const int* in_sizes, int n_in,
                              void* d_out, int out_size) {
    (void)in_sizes; (void)n_in; (void)out_size;
    const float* rgb = (const float*)d_in[0];
    const float* dep = (const float*)d_in[1];
    const float* Wq  = (const float*)d_in[2];
    const float* bq  = (const float*)d_in[3];
    const float* Wk  = (const float*)d_in[4];
    const float* bk  = (const float*)d_in[5];
    const float* Wv  = (const float*)d_in[6];
    const float* bv  = (const float*)d_in[7];
    float* out = (float*)d_out;

    void* p;
    __half *rgb_h, *dep_h, *wt, *q, *k, *vt, *ph;
    float *partial, *rinv;
    cudaGetSymbolAddress(&p, g_rgb);     rgb_h   = (__half*)p;
    cudaGetSymbolAddress(&p, g_dep);     dep_h   = (__half*)p;
    cudaGetSymbolAddress(&p, g_wt);      wt      = (__half*)p;
    cudaGetSymbolAddress(&p, g_q);       q       = (__half*)p;
    cudaGetSymbolAddress(&p, g_k);       k       = (__half*)p;
    cudaGetSymbolAddress(&p, g_vt);      vt      = (__half*)p;
    cudaGetSymbolAddress(&p, g_p);       ph      = (__half*)p;
    cudaGetSymbolAddress(&p, g_partial); partial = (float*)p;
    cudaGetSymbolAddress(&p, g_rinv);    rinv    = (float*)p;

    constexpr int SMEM2 = 2 * STAGE_B;   // 55296
    constexpr int SMEM4 = 4 * STAGE_B;   // 110592
    cudaFuncSetAttribute((const void*)gemm_t<0, 512, 2, 3>,
                         cudaFuncAttributeMaxDynamicSharedMemorySize, SMEM2);
    cudaFuncSetAttribute((const void*)gemm_t<1, 512, 2, 3>,
                         cudaFuncAttributeMaxDynamicSharedMemorySize, SMEM2);
    cudaFuncSetAttribute((const void*)gemm_t<3, 4096, 4, 2>,
                         cudaFuncAttributeMaxDynamicSharedMemorySize, SMEM4);
    cudaFuncSetAttribute((const void*)scores_k,
                         cudaFuncAttributeMaxDynamicSharedMemorySize, S_SMEM);

    // Launch 1: all conversions
    const int workItems = 2 * NV4 + 3 * WCNT;
    convert_all<<<(workItems + 255) / 256, 256>>>(rgb, dep, Wq, Wk, Wv,
                                                  rgb_h, dep_h, wt);

    // Launches 2-3: Q and K projections
    dim3 gProj(R_ / 128, C_ / 64, 1);   // (128, 8)
    gemm_t<0, 512, 2, 3><<<gProj, 256, SMEM2>>>(rgb_h, wt,
        0, 0, bq, nullptr, q, nullptr);
    gemm_t<0, 512, 2, 3><<<gProj, 256, SMEM2>>>(dep_h, wt + C_ * C_,
        0, 0, bk, nullptr, k, nullptr);

    // Launch 4 (ncu target): scores + exp2.  scale2 = log2(e)/sqrt(C)
    dim3 gS(N_ / 128, M_ / 128, B_);   // (32, 32, 4)
    scores_k<<<gS, 128, S_SMEM>>>(q, k, 0.06376237236133904f, ph, partial);

    // Launch 5: V projection
    gemm_t<1, 512, 2, 3><<<gProj, 256, SMEM2>>>(dep_h, wt + 2 * C_ * C_,
        0, 0, bv, nullptr, vt, nullptr);   // V^T

    // Launch 6: rowsum -> 1/sum
    rowsum_kernel<<<R_ / 256, 256>>>(partial, rinv);

    // Launch 7: O = (P V) * rinv[row]
    dim3 gO(N_ / 128, C_ / 64, B_);   // (32, 8, 4)
    gemm_t<3, 4096, 4, 2><<<gO, 256, SMEM4>>>(ph, vt,
        NM_, (long)C_ * M_, nullptr, out, nullptr, rinv);
}